// round 3
// baseline (speedup 1.0000x reference)
#include <cuda_runtime.h>

#define N_MAX 100000
#define E_MAX 600000
#define HF 128

// ---------------- scratch (static __device__ — no allocation) ----------------
__device__ __align__(16) float d_bufA[N_MAX * HF];
__device__ __align__(16) float d_bufB[N_MAX * HF];
__device__ int   d_cnt[N_MAX];
__device__ int   d_incl[N_MAX];
__device__ int   d_rs[N_MAX + 1];
__device__ int   d_cursor[N_MAX];
__device__ int   d_csr[E_MAX];
__device__ float d_dinv[N_MAX];
__device__ float d_sc[N_MAX];     // dinv/deg
__device__ int   d_bsum[256];
__device__ int   d_bpref[256];

// ---------------- preprocessing: CSR-by-target + degree terms ----------------
__global__ void k_init(int n) {
    int i = blockIdx.x * blockDim.x + threadIdx.x;
    if (i < n) d_cnt[i] = 0;
}

// edge_index is INT32 (JAX default x64-disabled: jnp.int64 request yields int32)
__global__ void k_hist(const int* __restrict__ col, int e, int n) {
    int i = blockIdx.x * blockDim.x + threadIdx.x;
    if (i < e) {
        int c = col[i];
        if (c >= 0 && c < n) atomicAdd(&d_cnt[c], 1);
    }
}

__global__ void k_scan1(int n) {
    __shared__ int s[1024];
    int t = threadIdx.x;
    int i = blockIdx.x * 1024 + t;
    s[t] = (i < n) ? d_cnt[i] : 0;
    __syncthreads();
    for (int off = 1; off < 1024; off <<= 1) {
        int a = 0;
        if (t >= off) a = s[t - off];
        __syncthreads();
        s[t] += a;
        __syncthreads();
    }
    if (i < n) d_incl[i] = s[t];
    if (t == 1023) d_bsum[blockIdx.x] = s[1023];
}

__global__ void k_scan2(int nb) {
    if (threadIdx.x == 0) {
        int run = 0;
        for (int b = 0; b < nb; b++) { d_bpref[b] = run; run += d_bsum[b]; }
    }
}

__global__ void k_scan3(int n) {
    int i = blockIdx.x * blockDim.x + threadIdx.x;
    if (i >= n) return;
    int gi = d_incl[i] + d_bpref[i >> 10];
    int c  = d_cnt[i];
    int st = gi - c;
    d_rs[i] = st;
    d_cursor[i] = st;
    if (i == n - 1) d_rs[n] = gi;
    float deg = (float)(c + 1);          // degree incl. self-loop
    float di = rsqrtf(deg);
    d_dinv[i] = di;
    d_sc[i]   = di / deg;
}

__global__ void k_scatter(const int* __restrict__ ei, int e, int n) {
    int i = blockIdx.x * blockDim.x + threadIdx.x;
    if (i >= e) return;
    int c = ei[e + i];  // col (target)
    int r = ei[i];      // row (source)
    if (c < 0 || c >= n || r < 0 || r >= n) return;
    int pos = atomicAdd(&d_cursor[c], 1);
    d_csr[pos] = r;
}

// ---------------- 128x128xK=128 fp32 GEMM ----------------
// d_bufB = rowscale * (A @ W^T + bias), optional relu.
// Block: 128 rows x 128 cols, 256 threads, 8x8 microtile, K in 4 chunks of 32.
// Static smem only (~33KB). As padded (33), Bs XOR-swizzled (j^k): all smem
// stores and inner-loop loads are bank-conflict-free.
__global__ void __launch_bounds__(256) k_gemm(
    const float* __restrict__ Aopt,        // nullptr -> read d_bufA
    const float* __restrict__ W,
    const float* __restrict__ bias,
    const float* __restrict__ colscale,    // nullptr or [128]
    int use_dinv, int relu, int n)
{
    __shared__ float As[128 * 33];
    __shared__ float Bs[32 * 128];

    const float* A = Aopt ? Aopt : d_bufA;
    float* out = d_bufB;
    int tid = threadIdx.x;
    int row0 = blockIdx.x * 128;
    int tx = tid & 15, ty = tid >> 4;

    float acc[8][8];
    #pragma unroll
    for (int i = 0; i < 8; i++)
        #pragma unroll
        for (int j = 0; j < 8; j++) acc[i][j] = 0.f;

    const float4* A4 = (const float4*)A;
    const float4* W4 = (const float4*)W;

    for (int kc = 0; kc < 4; kc++) {
        // --- load A chunk [128 rows x 32 k] ---
        #pragma unroll
        for (int it = 0; it < 4; ++it) {
            int idx = tid + it * 256;
            int r = idx >> 3, c4 = idx & 7;       // 8 float4 per row-chunk
            float4 v = make_float4(0.f, 0.f, 0.f, 0.f);
            int gr = row0 + r;
            if (gr < n) v = A4[gr * 32 + kc * 8 + c4];
            if (colscale) {
                int cb = kc * 32 + c4 * 4;
                v.x *= colscale[cb + 0];
                v.y *= colscale[cb + 1];
                v.z *= colscale[cb + 2];
                v.w *= colscale[cb + 3];
            }
            int base = r * 33 + c4 * 4;
            As[base + 0] = v.x;
            As[base + 1] = v.y;
            As[base + 2] = v.z;
            As[base + 3] = v.w;
        }
        // --- load W chunk transposed with XOR swizzle: Bs[k][j^k] = W[j][kc*32+k] ---
        #pragma unroll
        for (int it = 0; it < 4; ++it) {
            int idx = tid + it * 256;
            int j = idx >> 3, kq = idx & 7;
            float4 v = W4[j * 32 + kc * 8 + kq];
            int k0 = kq * 4;
            Bs[(k0 + 0) * 128 + (j ^ (k0 + 0))] = v.x;
            Bs[(k0 + 1) * 128 + (j ^ (k0 + 1))] = v.y;
            Bs[(k0 + 2) * 128 + (j ^ (k0 + 2))] = v.z;
            Bs[(k0 + 3) * 128 + (j ^ (k0 + 3))] = v.w;
        }
        __syncthreads();

        #pragma unroll
        for (int k = 0; k < 32; k++) {
            float a[8], b[8];
            #pragma unroll
            for (int ii = 0; ii < 8; ii++) a[ii] = As[(ty + ii * 16) * 33 + k];
            #pragma unroll
            for (int jj = 0; jj < 8; jj++) b[jj] = Bs[k * 128 + ((tx + jj * 16) ^ k)];
            #pragma unroll
            for (int ii = 0; ii < 8; ii++)
                #pragma unroll
                for (int jj = 0; jj < 8; jj++)
                    acc[ii][jj] += a[ii] * b[jj];
        }
        __syncthreads();
    }

    #pragma unroll
    for (int ii = 0; ii < 8; ii++) {
        int gr = row0 + ty + ii * 16;
        if (gr >= n) continue;
        float rs = use_dinv ? d_dinv[gr] : 1.f;
        #pragma unroll
        for (int jj = 0; jj < 8; jj++) {
            int jc = tx + jj * 16;
            float v = (acc[ii][jj] + bias[jc]) * rs;
            if (relu) v = fmaxf(v, 0.f);
            out[gr * 128 + jc] = v;
        }
    }
}

// ---------------- aggregation: bufA[c] = relu(sc[c]*(bufB[c]+sum bufB[src]) + bc) ----------------
__global__ void k_agg(const float* __restrict__ bc, int n)
{
    int w = (blockIdx.x * blockDim.x + threadIdx.x) >> 5;
    int lane = threadIdx.x & 31;
    if (w >= n) return;
    const float4* g = (const float4*)d_bufB;
    float4 s = g[w * 32 + lane];   // self-loop term
    int beg = d_rs[w], end = d_rs[w + 1];
    for (int e = beg; e < end; ++e) {
        int src = d_csr[e];
        float4 v = g[src * 32 + lane];
        s.x += v.x; s.y += v.y; s.z += v.z; s.w += v.w;
    }
    float kf = d_sc[w];
    float bx = bc[lane * 4 + 0], by = bc[lane * 4 + 1];
    float bz = bc[lane * 4 + 2], bw = bc[lane * 4 + 3];
    float4 o;
    o.x = fmaxf(kf * s.x + bx, 0.f);
    o.y = fmaxf(kf * s.y + by, 0.f);
    o.z = fmaxf(kf * s.z + bz, 0.f);
    o.w = fmaxf(kf * s.w + bw, 0.f);
    ((float4*)d_bufA)[w * 32 + lane] = o;
}

// ---------------- final linear (H=128 -> C=40) + log_softmax, one warp/row ----------------
__global__ void __launch_bounds__(256) k_lin2(
    const float* __restrict__ W2, const float* __restrict__ b2,
    float* __restrict__ out, int n)
{
    __shared__ __align__(16) float Ws[40 * 129];   // pad 129: conflict-free row reads
    __shared__ __align__(16) float rowbuf[8][128];
    int tid = threadIdx.x;
    for (int idx = tid; idx < 40 * 128; idx += 256) {
        int c = idx >> 7, k = idx & 127;
        Ws[c * 129 + k] = W2[idx];
    }
    __syncthreads();

    int lane = tid & 31, w = tid >> 5;
    int row = blockIdx.x * 8 + w;
    if (row >= n) return;

    float4 hv = ((const float4*)d_bufB)[row * 32 + lane];
    rowbuf[w][lane * 4 + 0] = hv.x;
    rowbuf[w][lane * 4 + 1] = hv.y;
    rowbuf[w][lane * 4 + 2] = hv.z;
    rowbuf[w][lane * 4 + 3] = hv.w;
    __syncwarp();

    int c1 = 32 + (lane & 7);
    float v0 = b2[lane];
    float v1 = b2[c1];
    #pragma unroll 8
    for (int k = 0; k < 128; k++) {
        float hk = rowbuf[w][k];
        v0 += hk * Ws[lane * 129 + k];
        v1 += hk * Ws[c1 * 129 + k];
    }
    float m = fmaxf(v0, (lane < 8) ? v1 : -1e30f);
    #pragma unroll
    for (int o = 16; o; o >>= 1) m = fmaxf(m, __shfl_xor_sync(0xffffffffu, m, o));
    float e0 = __expf(v0 - m);
    float e1 = (lane < 8) ? __expf(v1 - m) : 0.f;
    float ssum = e0 + e1;
    #pragma unroll
    for (int o = 16; o; o >>= 1) ssum += __shfl_xor_sync(0xffffffffu, ssum, o);
    float ls = m + __logf(ssum);
    out[row * 40 + lane] = v0 - ls;
    if (lane < 8) out[row * 40 + 32 + lane] = v1 - ls;
}

// ---------------- launch ----------------
extern "C" void kernel_launch(void* const* d_in, const int* in_sizes, int n_in,
                              void* d_out, int out_size)
{
    const float* x    = (const float*)d_in[0];
    const int*   ei   = (const int*)d_in[1];     // int32! (JAX x64 disabled)
    const float* imp  = (const float*)d_in[2];
    const float* W1   = (const float*)d_in[3];
    const float* bl1  = (const float*)d_in[4];
    const float* bc1  = (const float*)d_in[5];
    const float* W2   = (const float*)d_in[6];
    const float* bl2  = (const float*)d_in[7];
    const float* bc2  = (const float*)d_in[8];
    const float* W3   = (const float*)d_in[9];
    const float* bl3  = (const float*)d_in[10];
    const float* bc3  = (const float*)d_in[11];
    const float* Wl1  = (const float*)d_in[12];
    const float* bli1 = (const float*)d_in[13];
    const float* Wl2  = (const float*)d_in[14];
    const float* bli2 = (const float*)d_in[15];
    int n = in_sizes[0] / HF;
    int e = in_sizes[1] / 2;
    float* out = (float*)d_out;

    // preprocessing (CSR build + degree scaling); reused across all 3 conv layers
    k_init   <<<(n + 255) / 256, 256>>>(n);
    k_hist   <<<(e + 255) / 256, 256>>>(ei + e, e, n);
    int nb = (n + 1023) / 1024;
    k_scan1  <<<nb, 1024>>>(n);
    k_scan2  <<<1, 32>>>(nb);
    k_scan3  <<<(n + 255) / 256, 256>>>(n);
    k_scatter<<<(e + 255) / 256, 256>>>(ei, e, n);

    int gblocks = (n + 127) / 128;
    int ablocks = (n + 7) / 8;

    // conv1 (importance folded into A load; dinv rowscale folded into GEMM epilogue)
    k_gemm<<<gblocks, 256>>>(x,       W1,  bl1,  imp,     1, 0, n);
    k_agg <<<ablocks, 256>>>(bc1, n);
    // conv2
    k_gemm<<<gblocks, 256>>>(nullptr, W2,  bl2,  nullptr, 1, 0, n);
    k_agg <<<ablocks, 256>>>(bc2, n);
    // conv3
    k_gemm<<<gblocks, 256>>>(nullptr, W3,  bl3,  nullptr, 1, 0, n);
    k_agg <<<ablocks, 256>>>(bc3, n);
    // lin1 + relu
    k_gemm<<<gblocks, 256>>>(nullptr, Wl1, bli1, nullptr, 0, 1, n);
    // lin2 + log_softmax
    k_lin2<<<ablocks, 256>>>(Wl2, bli2, out, n);
}